// round 7
// baseline (speedup 1.0000x reference)
#include <cuda_runtime.h>
#include <cuda_bf16.h>
#include <math.h>
#include <stdint.h>

// Problem constants (fixed by the dataset)
#define BATCH 4
#define SEQ   4096
#define DM    512
#define NH    8
#define NP    4
#define HD    64              // DM / NH
#define ROWS  (BATCH * SEQ)   // 16384

// ---------------------------------------------------------------------------
// Scratch (device globals; no allocation allowed in kernel_launch)
// ---------------------------------------------------------------------------
__device__ __align__(16) float g_Q  [ROWS * DM];
__device__ __align__(16) float g_K  [ROWS * DM];
__device__ __align__(16) float g_V  [ROWS * DM];
__device__ __align__(16) float g_OFF[ROWS * NH * NP];
__device__ __align__(16) float g_LOG[ROWS * NH * NP];
__device__ __align__(16) float g_ATT[ROWS * DM];
// bf16 hi/lo splits: weights [4 matrices] and activations [2 buffers]
__device__ __align__(16) __nv_bfloat16 g_Wh[4][DM * DM];
__device__ __align__(16) __nv_bfloat16 g_Wl[4][DM * DM];
__device__ __align__(16) __nv_bfloat16 g_Ah[2][ROWS * DM];
__device__ __align__(16) __nv_bfloat16 g_Al[2][ROWS * DM];

// ---------------------------------------------------------------------------
// PTX helpers (baseline sm_80-class features only — valid at .target sm_103)
// ---------------------------------------------------------------------------
__device__ __forceinline__ uint32_t smem_u32(const void* p) {
    uint32_t a;
    asm("{ .reg .u64 t; cvta.to.shared.u64 t, %1; cvt.u32.u64 %0, t; }" : "=r"(a) : "l"(p));
    return a;
}
__device__ __forceinline__ void cp16(uint32_t s, const void* g) {
    asm volatile("cp.async.cg.shared.global [%0], [%1], 16;" :: "r"(s), "l"(g));
}
#define CP_COMMIT()   asm volatile("cp.async.commit_group;" ::: "memory")
#define CP_WAIT(n)    asm volatile("cp.async.wait_group %0;" :: "n"(n) : "memory")

#define LDSM4(r, a) \
    asm volatile("ldmatrix.sync.aligned.m8n8.x4.shared.b16 {%0,%1,%2,%3}, [%4];" \
                 : "=r"((r)[0]), "=r"((r)[1]), "=r"((r)[2]), "=r"((r)[3]) : "r"(a))
#define LDSM2(r, a) \
    asm volatile("ldmatrix.sync.aligned.m8n8.x2.shared.b16 {%0,%1}, [%2];" \
                 : "=r"((r)[0]), "=r"((r)[1]) : "r"(a))

#define MMA_BF16(d, a, b) \
    asm volatile("mma.sync.aligned.m16n8k16.row.col.f32.bf16.bf16.f32 " \
                 "{%0,%1,%2,%3}, {%4,%5,%6,%7}, {%8,%9}, {%0,%1,%2,%3};" \
                 : "+f"((d)[0]), "+f"((d)[1]), "+f"((d)[2]), "+f"((d)[3]) \
                 : "r"((a)[0]), "r"((a)[1]), "r"((a)[2]), "r"((a)[3]), \
                   "r"((b)[0]), "r"((b)[1]))

// ---------------------------------------------------------------------------
// fp32 -> bf16 hi/lo split (elementwise). n_elems must be divisible by 1024.
// ---------------------------------------------------------------------------
__global__ __launch_bounds__(256)
void conv_bf16(const float* __restrict__ X,
               __nv_bfloat16* __restrict__ Xh,
               __nv_bfloat16* __restrict__ Xl)
{
    const size_t i = ((size_t)blockIdx.x * 256 + threadIdx.x) * 4;
    const float4 f = *(const float4*)(X + i);

    __nv_bfloat162 h01 = __floats2bfloat162_rn(f.x, f.y);
    __nv_bfloat162 h23 = __floats2bfloat162_rn(f.z, f.w);
    float2 hf01 = __bfloat1622float2(h01);
    float2 hf23 = __bfloat1622float2(h23);
    __nv_bfloat162 l01 = __floats2bfloat162_rn(f.x - hf01.x, f.y - hf01.y);
    __nv_bfloat162 l23 = __floats2bfloat162_rn(f.z - hf23.x, f.w - hf23.y);

    uint2 hv, lv;
    hv.x = *(uint32_t*)&h01; hv.y = *(uint32_t*)&h23;
    lv.x = *(uint32_t*)&l01; lv.y = *(uint32_t*)&l23;
    *(uint2*)(Xh + i) = hv;
    *(uint2*)(Xl + i) = lv;
}

// ---------------------------------------------------------------------------
// Tensor-core GEMM (NT): C[m,n] = sum_k A[m,k]*B[n,k] + bias[n]
// fp32 emulated via 3-pass bf16: Ah*Bh + Ah*Bl + Al*Bh (all pre-split).
// Tile 128x128, BK=32, 256 threads (8 warps, 2x4), m16n8k16 fragments.
// SMEM rows padded to 80B -> conflict-free ldmatrix.
// 3-stage cp.async pipeline, ONE __syncthreads per chunk.
// ---------------------------------------------------------------------------
#define ROWB   80                  // bytes per 32-bf16 SMEM row (64B data + pad)
#define TILE_B (128 * ROWB)        // 10240 B per operand tile
#define STG_B  (4 * TILE_B)        // 40960 B: Ah | Al | Bh | Bl
#define NSTAGE 3
#define GEMM_SMEM (NSTAGE * STG_B) // 122880 B

__global__ __launch_bounds__(256)
void gemm_mma(const __nv_bfloat16* __restrict__ Ah,
              const __nv_bfloat16* __restrict__ Al,
              const __nv_bfloat16* __restrict__ Bh,
              const __nv_bfloat16* __restrict__ Bl,
              const float* __restrict__ bias,
              float* __restrict__ C)
{
    extern __shared__ char sm[];
    const uint32_t sb = smem_u32(sm);
    const int tid  = threadIdx.x;
    const int lane = tid & 31;
    const int wid  = tid >> 5;
    const int wr   = wid >> 2;     // warp row 0..1  (64 rows each)
    const int wc   = wid & 3;      // warp col 0..3  (32 cols each)

    const int bm = blockIdx.y * 128;
    const int bn = blockIdx.x * 128;

    const __nv_bfloat16* gAh = Ah + (size_t)bm * DM;
    const __nv_bfloat16* gAl = Al + (size_t)bm * DM;
    const __nv_bfloat16* gBh = Bh + (size_t)bn * DM;
    const __nv_bfloat16* gBl = Bl + (size_t)bn * DM;

    float acc[4][4][4];
#pragma unroll
    for (int i = 0; i < 4; i++)
#pragma unroll
        for (int j = 0; j < 4; j++)
#pragma unroll
            for (int k = 0; k < 4; k++) acc[i][j][k] = 0.0f;

    // --- staging: thread t stages row t>>1, two of four 16B chunks ---
    const int srow = tid >> 1;
#define STAGE(cc, sbuf) do {                                                  \
        const uint32_t buf = sb + (uint32_t)(sbuf) * STG_B;                   \
        const int kb = (cc) * 32;                                             \
        _Pragma("unroll")                                                     \
        for (int jj = 0; jj < 2; jj++) {                                      \
            const int j = (tid & 1) + jj * 2;                                 \
            const size_t go = (size_t)srow * DM + kb + j * 8;                 \
            const uint32_t so = (uint32_t)(srow * ROWB + j * 16);             \
            cp16(buf + so,              gAh + go);                            \
            cp16(buf + TILE_B + so,     gAl + go);                            \
            cp16(buf + 2*TILE_B + so,   gBh + go);                            \
            cp16(buf + 3*TILE_B + so,   gBl + go);                            \
        }                                                                     \
        CP_COMMIT();                                                          \
    } while (0)

    STAGE(0, 0);
    STAGE(1, 1);

    const int al15 = lane & 15;          // A ldmatrix row-in-tile
    const int ac   = lane >> 4;          // A ldmatrix 16B chunk select
    const int bl7  = lane & 7;           // B ldmatrix row-in-tile
    const int bc   = (lane >> 3) & 1;    // B chunk select (lanes 0..15)

    int rbuf = 0, wbuf = 2;
    for (int c = 0; c < 16; c++) {
        if (c < 15) { CP_WAIT(1); } else { CP_WAIT(0); }
        __syncthreads();
        if (c + 2 < 16) STAGE(c + 2, wbuf);   // overlaps with compute below

        const uint32_t buf  = sb + (uint32_t)rbuf * STG_B;
        const uint32_t ahB  = buf;
        const uint32_t alB  = buf + TILE_B;
        const uint32_t bhB  = buf + 2 * TILE_B;
        const uint32_t blB  = buf + 3 * TILE_B;

#pragma unroll
        for (int ks = 0; ks < 2; ks++) {
            uint32_t fah[4][4], fal[4][4], fbh[4][2], fbl[4][2];
#pragma unroll
            for (int mt = 0; mt < 4; mt++) {
                const uint32_t off =
                    (uint32_t)((wr * 64 + mt * 16 + al15) * ROWB
                               + (2 * ks + ac) * 16);
                LDSM4(fah[mt], ahB + off);
                LDSM4(fal[mt], alB + off);
            }
#pragma unroll
            for (int nt = 0; nt < 4; nt++) {
                const uint32_t off =
                    (uint32_t)((wc * 32 + nt * 8 + bl7) * ROWB
                               + (2 * ks + bc) * 16);
                LDSM2(fbh[nt], bhB + off);
                LDSM2(fbl[nt], blB + off);
            }
            // Pass-major ordering: 16 independent MMAs between reuses of any
            // accumulator -> no RAW chains on the tensor pipe.
#pragma unroll
            for (int mt = 0; mt < 4; mt++)
#pragma unroll
                for (int nt = 0; nt < 4; nt++)
                    MMA_BF16(acc[mt][nt], fah[mt], fbh[nt]);
#pragma unroll
            for (int mt = 0; mt < 4; mt++)
#pragma unroll
                for (int nt = 0; nt < 4; nt++)
                    MMA_BF16(acc[mt][nt], fah[mt], fbl[nt]);
#pragma unroll
            for (int mt = 0; mt < 4; mt++)
#pragma unroll
                for (int nt = 0; nt < 4; nt++)
                    MMA_BF16(acc[mt][nt], fal[mt], fbh[nt]);
        }

        rbuf = (rbuf == NSTAGE - 1) ? 0 : rbuf + 1;
        wbuf = (wbuf == NSTAGE - 1) ? 0 : wbuf + 1;
    }

    // Epilogue: m16n8 acc fragment -> C with bias
    const int gr = lane >> 2;
    const int gc = (lane & 3) * 2;
#pragma unroll
    for (int mt = 0; mt < 4; mt++) {
        const int r0 = bm + wr * 64 + mt * 16 + gr;
#pragma unroll
        for (int nt = 0; nt < 4; nt++) {
            const int c0 = bn + wc * 32 + nt * 8 + gc;
            const float b0 = bias[c0], b1 = bias[c0 + 1];
            float2 v0, v1;
            v0.x = acc[mt][nt][0] + b0; v0.y = acc[mt][nt][1] + b1;
            v1.x = acc[mt][nt][2] + b0; v1.y = acc[mt][nt][3] + b1;
            *(float2*)(C + (size_t)r0 * DM + c0)       = v0;
            *(float2*)(C + (size_t)(r0 + 8) * DM + c0) = v1;
        }
    }
#undef STAGE
}

// ---------------------------------------------------------------------------
// Small projections: OFF = q_in @ Woff^T + boff, LOG = q_in @ Wa^T + ba
// ---------------------------------------------------------------------------
__global__ __launch_bounds__(512)
void proj_small(const float* __restrict__ A,
                const float* __restrict__ Woff, const float* __restrict__ boff,
                const float* __restrict__ Wa,   const float* __restrict__ ba,
                float* __restrict__ OFF, float* __restrict__ LOG)
{
    __shared__ float sA[8][DM];
    const int tid  = threadIdx.x;
    const int r    = tid >> 6;      // 0..7
    const int n    = tid & 63;      // 0..63
    const int row0 = blockIdx.x * 8;

    const float4* Ag  = (const float4*)(A + (size_t)row0 * DM);
    float4*       sAv = (float4*)&sA[0][0];
    sAv[tid]       = Ag[tid];
    sAv[tid + 512] = Ag[tid + 512];
    __syncthreads();

    const float* wrow = (n < 32) ? (Woff + (size_t)n * DM)
                                 : (Wa   + (size_t)(n - 32) * DM);
    float sum = 0.0f;
#pragma unroll 8
    for (int k = 0; k < DM; k++) sum += sA[r][k] * __ldg(&wrow[k]);
    sum += (n < 32) ? boff[n] : ba[n - 32];

    const size_t oi = (size_t)(row0 + r) * 32 + (n & 31);
    if (n < 32) OFF[oi] = sum;
    else        LOG[oi] = sum;
}

// ---------------------------------------------------------------------------
// Deformable attention core. One warp per (b, l, h); lane owns dims d, d+32.
// ---------------------------------------------------------------------------
__global__ __launch_bounds__(256)
void deform_attn(const float* __restrict__ Q,
                 const float* __restrict__ Kx,
                 const float* __restrict__ Vx,
                 const float* __restrict__ OFF,
                 const float* __restrict__ LOG,
                 float* __restrict__ OUT)
{
    const int warp = (blockIdx.x * blockDim.x + threadIdx.x) >> 5;
    const int lane = threadIdx.x & 31;

    const int h  = warp & 7;           // head
    const int bl = warp >> 3;          // b*SEQ + l
    const int l  = bl & (SEQ - 1);
    const int b  = bl >> 12;

    const float* qrow = Q + (size_t)bl * DM + h * HD;
    const float  q0 = qrow[lane];
    const float  q1 = qrow[lane + 32];

    const float* Kb = Kx + (size_t)b * SEQ * DM;
    const float* Vb = Vx + (size_t)b * SEQ * DM;

    int   ia[NP], ib[NP];
    float wf[NP], dot[NP];

#pragma unroll
    for (int p = 0; p < NP; p++) {
        const float off = OFF[(size_t)bl * 32 + h * NP + p];
        float idx = fminf(fmaxf((float)l + off, 0.0f), (float)(SEQ - 1));
        float f0  = floorf(idx);
        int   a0  = (int)f0;
        a0 = max(0, min(a0, SEQ - 1));
        const int   a1 = min(a0 + 1, SEQ - 1);
        const float w  = idx - (float)a0;
        ia[p] = a0; ib[p] = a1; wf[p] = w;

        const float* k0 = Kb + (size_t)a0 * DM + h * HD;
        const float* k1 = Kb + (size_t)a1 * DM + h * HD;
        const float ks0 = (1.0f - w) * k0[lane]      + w * k1[lane];
        const float ks1 = (1.0f - w) * k0[lane + 32] + w * k1[lane + 32];

        float d = q0 * ks0 + q1 * ks1;
#pragma unroll
        for (int s = 16; s > 0; s >>= 1)
            d += __shfl_xor_sync(0xffffffffu, d, s);
        dot[p] = d * 0.125f + LOG[(size_t)bl * 32 + h * NP + p];
    }

    float m = fmaxf(fmaxf(dot[0], dot[1]), fmaxf(dot[2], dot[3]));
    float e[NP], ssum = 0.0f;
#pragma unroll
    for (int p = 0; p < NP; p++) { e[p] = expf(dot[p] - m); ssum += e[p]; }
    const float inv = 1.0f / ssum;

    float o0 = 0.0f, o1 = 0.0f;
#pragma unroll
    for (int p = 0; p < NP; p++) {
        const float* v0 = Vb + (size_t)ia[p] * DM + h * HD;
        const float* v1 = Vb + (size_t)ib[p] * DM + h * HD;
        const float w  = wf[p];
        const float wp = e[p] * inv;
        o0 += wp * ((1.0f - w) * v0[lane]      + w * v1[lane]);
        o1 += wp * ((1.0f - w) * v0[lane + 32] + w * v1[lane + 32]);
    }

    float* orow = OUT + (size_t)bl * DM + h * HD;
    orow[lane]      = o0;
    orow[lane + 32] = o1;
}

// ---------------------------------------------------------------------------
// Launch. Order matters for profiling: the harness issues 2 internal launches
// first and ncu (-s 5 -c 1) captures OUR 4th launch -> put gemm_mma(Q) there.
// ---------------------------------------------------------------------------
extern "C" void kernel_launch(void* const* d_in, const int* in_sizes, int n_in,
                              void* d_out, int out_size)
{
    const float* q_in  = (const float*)d_in[0];
    const float* kv_in = (const float*)d_in[1];
    const float* Wq    = (const float*)d_in[2];
    const float* bq    = (const float*)d_in[3];
    const float* Wk    = (const float*)d_in[4];
    const float* bk    = (const float*)d_in[5];
    const float* Wv    = (const float*)d_in[6];
    const float* bv    = (const float*)d_in[7];
    const float* Woff  = (const float*)d_in[8];
    const float* boff  = (const float*)d_in[9];
    const float* Wa    = (const float*)d_in[10];
    const float* ba    = (const float*)d_in[11];
    const float* Wo    = (const float*)d_in[12];
    const float* bo    = (const float*)d_in[13];
    float* out = (float*)d_out;

    float *Q, *K, *V, *OFF, *LOG, *ATT;
    __nv_bfloat16 *Wh, *Wl, *Ah, *Al;
    cudaGetSymbolAddress((void**)&Q,   g_Q);
    cudaGetSymbolAddress((void**)&K,   g_K);
    cudaGetSymbolAddress((void**)&V,   g_V);
    cudaGetSymbolAddress((void**)&OFF, g_OFF);
    cudaGetSymbolAddress((void**)&LOG, g_LOG);
    cudaGetSymbolAddress((void**)&ATT, g_ATT);
    cudaGetSymbolAddress((void**)&Wh,  g_Wh);
    cudaGetSymbolAddress((void**)&Wl,  g_Wl);
    cudaGetSymbolAddress((void**)&Ah,  g_Ah);
    cudaGetSymbolAddress((void**)&Al,  g_Al);

    cudaFuncSetAttribute(gemm_mma, cudaFuncAttributeMaxDynamicSharedMemorySize,
                         GEMM_SMEM);

    const int WSZ = DM * DM;      // 262144
    const size_t ASZ = (size_t)ROWS * DM;
    const int WGRID = WSZ / 1024; // 256
    const int AGRID = (int)(ASZ / 1024);

    dim3 gg(DM / 128, ROWS / 128);   // (4, 128)

    // idx 0-2: conversions needed for gemm Q
    conv_bf16<<<WGRID, 256>>>(Wq, Wh + 0 * WSZ, Wl + 0 * WSZ);
    conv_bf16<<<AGRID, 256>>>(q_in,  Ah,        Al);
    conv_bf16<<<AGRID, 256>>>(kv_in, Ah + ASZ,  Al + ASZ);

    // idx 3: gemm Q  <- captured by ncu
    gemm_mma<<<gg, 256, GEMM_SMEM>>>(Ah, Al, Wh + 0 * WSZ, Wl + 0 * WSZ, bq, Q);

    // remaining weight conversions
    conv_bf16<<<WGRID, 256>>>(Wk, Wh + 1 * WSZ, Wl + 1 * WSZ);
    conv_bf16<<<WGRID, 256>>>(Wv, Wh + 2 * WSZ, Wl + 2 * WSZ);
    conv_bf16<<<WGRID, 256>>>(Wo, Wh + 3 * WSZ, Wl + 3 * WSZ);

    gemm_mma<<<gg, 256, GEMM_SMEM>>>(Ah + ASZ, Al + ASZ,
                                     Wh + 1 * WSZ, Wl + 1 * WSZ, bk, K);
    gemm_mma<<<gg, 256, GEMM_SMEM>>>(Ah + ASZ, Al + ASZ,
                                     Wh + 2 * WSZ, Wl + 2 * WSZ, bv, V);

    proj_small<<<ROWS / 8, 512>>>(q_in, Woff, boff, Wa, ba, OFF, LOG);

    deform_attn<<<(ROWS * NH) / 8, 256>>>(Q, K, V, OFF, LOG, ATT);

    // Reuse activation buffer 0 for ATT
    conv_bf16<<<AGRID, 256>>>(ATT, Ah, Al);
    gemm_mma<<<gg, 256, GEMM_SMEM>>>(Ah, Al, Wh + 3 * WSZ, Wl + 3 * WSZ, bo, out);
}

// round 9
// speedup vs baseline: 4.2383x; 4.2383x over previous
#include <cuda_runtime.h>
#include <cuda_bf16.h>
#include <math.h>
#include <stdint.h>

// Problem constants (fixed by the dataset)
#define BATCH 4
#define SEQ   4096
#define DM    512
#define NH    8
#define NP    4
#define HD    64              // DM / NH
#define ROWS  (BATCH * SEQ)   // 16384

// ---------------------------------------------------------------------------
// Scratch (device globals; no allocation allowed in kernel_launch)
// ---------------------------------------------------------------------------
__device__ __align__(16) float g_Q  [ROWS * DM];
__device__ __align__(16) float g_K  [ROWS * DM];
__device__ __align__(16) float g_V  [ROWS * DM];
__device__ __align__(16) float g_OL [ROWS * 128];      // cols 0-31 OFF, 32-63 LOG
__device__ __align__(16) float g_bc [128];             // combined bias
// bf16 hi/lo splits: 4 big weights, combined (Woff;Wa;0) weight, 2 activations
__device__ __align__(16) __nv_bfloat16 g_Wh[4][DM * DM];
__device__ __align__(16) __nv_bfloat16 g_Wl[4][DM * DM];
__device__ __align__(16) __nv_bfloat16 g_Wch[128 * DM];
__device__ __align__(16) __nv_bfloat16 g_Wcl[128 * DM];
__device__ __align__(16) __nv_bfloat16 g_Ah[2][ROWS * DM];
__device__ __align__(16) __nv_bfloat16 g_Al[2][ROWS * DM];

// ---------------------------------------------------------------------------
// PTX helpers (baseline sm_80-class features only — valid at .target sm_103)
// ---------------------------------------------------------------------------
__device__ __forceinline__ uint32_t smem_u32(const void* p) {
    uint32_t a;
    asm("{ .reg .u64 t; cvta.to.shared.u64 t, %1; cvt.u32.u64 %0, t; }" : "=r"(a) : "l"(p));
    return a;
}
__device__ __forceinline__ void cp16(uint32_t s, const void* g) {
    asm volatile("cp.async.cg.shared.global [%0], [%1], 16;" :: "r"(s), "l"(g));
}
#define CP_COMMIT()   asm volatile("cp.async.commit_group;" ::: "memory")
#define CP_WAIT(n)    asm volatile("cp.async.wait_group %0;" :: "n"(n) : "memory")

#define LDSM4(r, a) \
    asm volatile("ldmatrix.sync.aligned.m8n8.x4.shared.b16 {%0,%1,%2,%3}, [%4];" \
                 : "=r"((r)[0]), "=r"((r)[1]), "=r"((r)[2]), "=r"((r)[3]) : "r"(a))
#define LDSM2(r, a) \
    asm volatile("ldmatrix.sync.aligned.m8n8.x2.shared.b16 {%0,%1}, [%2];" \
                 : "=r"((r)[0]), "=r"((r)[1]) : "r"(a))

#define MMA_BF16(d, a, b) \
    asm volatile("mma.sync.aligned.m16n8k16.row.col.f32.bf16.bf16.f32 " \
                 "{%0,%1,%2,%3}, {%4,%5,%6,%7}, {%8,%9}, {%0,%1,%2,%3};" \
                 : "+f"((d)[0]), "+f"((d)[1]), "+f"((d)[2]), "+f"((d)[3]) \
                 : "r"((a)[0]), "r"((a)[1]), "r"((a)[2]), "r"((a)[3]), \
                   "r"((b)[0]), "r"((b)[1]))

// fp32x4 -> bf16 hi/lo split, stored as uint2 pairs
__device__ __forceinline__ void split_store4(const float4 f,
                                             __nv_bfloat16* __restrict__ ph,
                                             __nv_bfloat16* __restrict__ pl)
{
    __nv_bfloat162 h01 = __floats2bfloat162_rn(f.x, f.y);
    __nv_bfloat162 h23 = __floats2bfloat162_rn(f.z, f.w);
    float2 a = __bfloat1622float2(h01);
    float2 b = __bfloat1622float2(h23);
    __nv_bfloat162 l01 = __floats2bfloat162_rn(f.x - a.x, f.y - a.y);
    __nv_bfloat162 l23 = __floats2bfloat162_rn(f.z - b.x, f.w - b.y);
    uint2 hv, lv;
    hv.x = *(uint32_t*)&h01; hv.y = *(uint32_t*)&h23;
    lv.x = *(uint32_t*)&l01; lv.y = *(uint32_t*)&l23;
    *(uint2*)ph = hv;
    *(uint2*)pl = lv;
}

// ---------------------------------------------------------------------------
// Activation split: fp32 -> bf16 hi/lo (elementwise)
// ---------------------------------------------------------------------------
__global__ __launch_bounds__(256)
void conv_bf16(const float* __restrict__ X,
               __nv_bfloat16* __restrict__ Xh,
               __nv_bfloat16* __restrict__ Xl)
{
    const size_t i = ((size_t)blockIdx.x * 256 + threadIdx.x) * 4;
    split_store4(*(const float4*)(X + i), Xh + i, Xl + i);
}

// ---------------------------------------------------------------------------
// All weight conversions in one launch:
//   blocks    0..1023: Wq/Wk/Wv/Wo -> g_Wh/g_Wl  (256 blocks each)
//   blocks 1024..1087: combined (Woff rows 0-31, Wa rows 32-63, zeros 64-127)
//   block  1088      : combined bias
// ---------------------------------------------------------------------------
__global__ __launch_bounds__(256)
void conv_weights(const float* __restrict__ Wq, const float* __restrict__ Wk,
                  const float* __restrict__ Wv, const float* __restrict__ Wo,
                  const float* __restrict__ Woff, const float* __restrict__ Wa,
                  const float* __restrict__ boff, const float* __restrict__ ba,
                  __nv_bfloat16* __restrict__ Wh, __nv_bfloat16* __restrict__ Wl,
                  __nv_bfloat16* __restrict__ Wch, __nv_bfloat16* __restrict__ Wcl,
                  float* __restrict__ bc)
{
    const int blk = blockIdx.x;
    if (blk < 1024) {
        const int m = blk >> 8;
        const float* W = (m == 0) ? Wq : (m == 1) ? Wk : (m == 2) ? Wv : Wo;
        const size_t i = ((size_t)(blk & 255) * 256 + threadIdx.x) * 4;
        split_store4(*(const float4*)(W + i),
                     Wh + (size_t)m * DM * DM + i,
                     Wl + (size_t)m * DM * DM + i);
    } else if (blk < 1088) {
        const size_t i = ((size_t)(blk - 1024) * 256 + threadIdx.x) * 4;
        const int row = (int)(i >> 9);
        const int ck  = (int)(i & 511);
        float4 f = make_float4(0.f, 0.f, 0.f, 0.f);
        if (row < 32)       f = *(const float4*)(Woff + (size_t)row * DM + ck);
        else if (row < 64)  f = *(const float4*)(Wa + (size_t)(row - 32) * DM + ck);
        split_store4(f, Wch + i, Wcl + i);
    } else {
        const int n = threadIdx.x;
        if (n < 128)
            bc[n] = (n < 32) ? boff[n] : (n < 64) ? ba[n - 32] : 0.f;
    }
}

// ---------------------------------------------------------------------------
// Tensor-core GEMM (NT): C[m,n] = sum_k A[m,k]*B[n,k] + bias[n]
// fp32 emulated via 3-pass bf16: Ah*Bh + Ah*Bl + Al*Bh (all pre-split).
// Tile 128x128, BK=32, 256 threads (8 warps, 2x4), m16n8k16 fragments.
// 3-stage cp.async pipeline, one __syncthreads per chunk. ldc = C row stride.
// ---------------------------------------------------------------------------
#define ROWB   80                  // bytes per 32-bf16 SMEM row (64B data + pad)
#define TILE_B (128 * ROWB)        // 10240 B per operand tile
#define STG_B  (4 * TILE_B)        // 40960 B: Ah | Al | Bh | Bl
#define NSTAGE 3
#define GEMM_SMEM (NSTAGE * STG_B) // 122880 B

__global__ __launch_bounds__(256)
void gemm_mma(const __nv_bfloat16* __restrict__ Ah,
              const __nv_bfloat16* __restrict__ Al,
              const __nv_bfloat16* __restrict__ Bh,
              const __nv_bfloat16* __restrict__ Bl,
              const float* __restrict__ bias,
              float* __restrict__ C, int ldc)
{
    extern __shared__ char sm[];
    const uint32_t sb = smem_u32(sm);
    const int tid  = threadIdx.x;
    const int lane = tid & 31;
    const int wid  = tid >> 5;
    const int wr   = wid >> 2;     // warp row 0..1  (64 rows each)
    const int wc   = wid & 3;      // warp col 0..3  (32 cols each)

    const int bm = blockIdx.y * 128;
    const int bn = blockIdx.x * 128;

    const __nv_bfloat16* gAh = Ah + (size_t)bm * DM;
    const __nv_bfloat16* gAl = Al + (size_t)bm * DM;
    const __nv_bfloat16* gBh = Bh + (size_t)bn * DM;
    const __nv_bfloat16* gBl = Bl + (size_t)bn * DM;

    float acc[4][4][4];
#pragma unroll
    for (int i = 0; i < 4; i++)
#pragma unroll
        for (int j = 0; j < 4; j++)
#pragma unroll
            for (int k = 0; k < 4; k++) acc[i][j][k] = 0.0f;

    const int srow = tid >> 1;
#define STAGE(cc, sbuf) do {                                                  \
        const uint32_t buf = sb + (uint32_t)(sbuf) * STG_B;                   \
        const int kb = (cc) * 32;                                             \
        _Pragma("unroll")                                                     \
        for (int jj = 0; jj < 2; jj++) {                                      \
            const int j = (tid & 1) + jj * 2;                                 \
            const size_t go = (size_t)srow * DM + kb + j * 8;                 \
            const uint32_t so = (uint32_t)(srow * ROWB + j * 16);             \
            cp16(buf + so,              gAh + go);                            \
            cp16(buf + TILE_B + so,     gAl + go);                            \
            cp16(buf + 2*TILE_B + so,   gBh + go);                            \
            cp16(buf + 3*TILE_B + so,   gBl + go);                            \
        }                                                                     \
        CP_COMMIT();                                                          \
    } while (0)

    STAGE(0, 0);
    STAGE(1, 1);

    const int al15 = lane & 15;
    const int ac   = lane >> 4;
    const int bl7  = lane & 7;
    const int bc   = (lane >> 3) & 1;

    int rbuf = 0, wbuf = 2;
    for (int c = 0; c < 16; c++) {
        if (c < 15) { CP_WAIT(1); } else { CP_WAIT(0); }
        __syncthreads();
        if (c + 2 < 16) STAGE(c + 2, wbuf);

        const uint32_t buf  = sb + (uint32_t)rbuf * STG_B;
        const uint32_t ahB  = buf;
        const uint32_t alB  = buf + TILE_B;
        const uint32_t bhB  = buf + 2 * TILE_B;
        const uint32_t blB  = buf + 3 * TILE_B;

#pragma unroll
        for (int ks = 0; ks < 2; ks++) {
            uint32_t fah[4][4], fal[4][4], fbh[4][2], fbl[4][2];
#pragma unroll
            for (int mt = 0; mt < 4; mt++) {
                const uint32_t off =
                    (uint32_t)((wr * 64 + mt * 16 + al15) * ROWB
                               + (2 * ks + ac) * 16);
                LDSM4(fah[mt], ahB + off);
                LDSM4(fal[mt], alB + off);
            }
#pragma unroll
            for (int nt = 0; nt < 4; nt++) {
                const uint32_t off =
                    (uint32_t)((wc * 32 + nt * 8 + bl7) * ROWB
                               + (2 * ks + bc) * 16);
                LDSM2(fbh[nt], bhB + off);
                LDSM2(fbl[nt], blB + off);
            }
#pragma unroll
            for (int mt = 0; mt < 4; mt++)
#pragma unroll
                for (int nt = 0; nt < 4; nt++)
                    MMA_BF16(acc[mt][nt], fah[mt], fbh[nt]);
#pragma unroll
            for (int mt = 0; mt < 4; mt++)
#pragma unroll
                for (int nt = 0; nt < 4; nt++)
                    MMA_BF16(acc[mt][nt], fah[mt], fbl[nt]);
#pragma unroll
            for (int mt = 0; mt < 4; mt++)
#pragma unroll
                for (int nt = 0; nt < 4; nt++)
                    MMA_BF16(acc[mt][nt], fal[mt], fbh[nt]);
        }

        rbuf = (rbuf == NSTAGE - 1) ? 0 : rbuf + 1;
        wbuf = (wbuf == NSTAGE - 1) ? 0 : wbuf + 1;
    }

    const int gr = lane >> 2;
    const int gc = (lane & 3) * 2;
#pragma unroll
    for (int mt = 0; mt < 4; mt++) {
        const int r0 = bm + wr * 64 + mt * 16 + gr;
#pragma unroll
        for (int nt = 0; nt < 4; nt++) {
            const int c0 = bn + wc * 32 + nt * 8 + gc;
            const float b0 = bias[c0], b1 = bias[c0 + 1];
            float2 v0, v1;
            v0.x = acc[mt][nt][0] + b0; v0.y = acc[mt][nt][1] + b1;
            v1.x = acc[mt][nt][2] + b0; v1.y = acc[mt][nt][3] + b1;
            *(float2*)(C + (size_t)r0 * ldc + c0)       = v0;
            *(float2*)(C + (size_t)(r0 + 8) * ldc + c0) = v1;
        }
    }
#undef STAGE
}

// ---------------------------------------------------------------------------
// Deformable attention core, vectorized.
// One warp per (bl, h). Lanes 0-15 own interpolation row a0, lanes 16-31 own
// a1; lane j holds dims [j*4, j*4+4) as float4. Output is written directly as
// bf16 hi/lo split (feeds the final GEMM without a separate conversion pass).
// ---------------------------------------------------------------------------
__global__ __launch_bounds__(256)
void deform_attn(const float* __restrict__ Q,
                 const float* __restrict__ Kx,
                 const float* __restrict__ Vx,
                 const float* __restrict__ OL,
                 __nv_bfloat16* __restrict__ Oh,
                 __nv_bfloat16* __restrict__ Ol)
{
    const int warp = blockIdx.x * 8 + (threadIdx.x >> 5);
    const int lane = threadIdx.x & 31;
    const int half = lane >> 4;        // 0: row a0, 1: row a1
    const int j    = lane & 15;        // float4 slot within head dim

    const int h  = warp & 7;
    const int bl = warp >> 3;
    const int l  = bl & (SEQ - 1);
    const int b  = bl >> 12;

    const size_t col = (size_t)h * HD + j * 4;
    const float4 qv   = *(const float4*)(Q + (size_t)bl * DM + col);
    const float4 offv = *(const float4*)(OL + (size_t)bl * 128 + h * 4);
    const float4 logv = *(const float4*)(OL + (size_t)bl * 128 + 32 + h * 4);

    const float* Kb = Kx + (size_t)b * SEQ * DM;
    const float* Vb = Vx + (size_t)b * SEQ * DM;

    const float offs[4] = {offv.x, offv.y, offv.z, offv.w};
    const float logs[4] = {logv.x, logv.y, logv.z, logv.w};

    int   r0[4], r1[4];
    float wf[4], dot[4];

#pragma unroll
    for (int p = 0; p < 4; p++) {
        float idx = fminf(fmaxf((float)l + offs[p], 0.0f), (float)(SEQ - 1));
        int   a0  = min((int)idx, SEQ - 1);      // idx >= 0 -> trunc == floor
        int   a1  = min(a0 + 1, SEQ - 1);
        float w   = idx - (float)a0;
        r0[p] = a0; r1[p] = a1; wf[p] = w;

        const int row = half ? a1 : a0;
        const float4 kv = *(const float4*)(Kb + (size_t)row * DM + col);
        float part = qv.x * kv.x + qv.y * kv.y + qv.z * kv.z + qv.w * kv.w;
#pragma unroll
        for (int s = 1; s < 16; s <<= 1)
            part += __shfl_xor_sync(0xffffffffu, part, s);
        const float other = __shfl_xor_sync(0xffffffffu, part, 16);
        const float d0 = half ? other : part;
        const float d1 = half ? part : other;
        dot[p] = ((1.0f - w) * d0 + w * d1) * 0.125f + logs[p];
    }

    // softmax over P=4 (identical in all lanes)
    const float m = fmaxf(fmaxf(dot[0], dot[1]), fmaxf(dot[2], dot[3]));
    float e[4], ss = 0.0f;
#pragma unroll
    for (int p = 0; p < 4; p++) { e[p] = expf(dot[p] - m); ss += e[p]; }
    const float inv = 1.0f / ss;

    float4 acc = make_float4(0.f, 0.f, 0.f, 0.f);
#pragma unroll
    for (int p = 0; p < 4; p++) {
        const int   row  = half ? r1[p] : r0[p];
        const float coef = e[p] * inv * (half ? wf[p] : (1.0f - wf[p]));
        const float4 vv  = *(const float4*)(Vb + (size_t)row * DM + col);
        acc.x += coef * vv.x; acc.y += coef * vv.y;
        acc.z += coef * vv.z; acc.w += coef * vv.w;
    }
    // combine halves
    acc.x += __shfl_xor_sync(0xffffffffu, acc.x, 16);
    acc.y += __shfl_xor_sync(0xffffffffu, acc.y, 16);
    acc.z += __shfl_xor_sync(0xffffffffu, acc.z, 16);
    acc.w += __shfl_xor_sync(0xffffffffu, acc.w, 16);

    if (half == 0) {
        const size_t oi = (size_t)bl * DM + col;
        split_store4(acc, Oh + oi, Ol + oi);
    }
}

// ---------------------------------------------------------------------------
// Launch. ncu captures our launch index 3 -> gemm_mma(Q).
// ---------------------------------------------------------------------------
extern "C" void kernel_launch(void* const* d_in, const int* in_sizes, int n_in,
                              void* d_out, int out_size)
{
    const float* q_in  = (const float*)d_in[0];
    const float* kv_in = (const float*)d_in[1];
    const float* Wq    = (const float*)d_in[2];
    const float* bq    = (const float*)d_in[3];
    const float* Wk    = (const float*)d_in[4];
    const float* bk    = (const float*)d_in[5];
    const float* Wv    = (const float*)d_in[6];
    const float* bv    = (const float*)d_in[7];
    const float* Woff  = (const float*)d_in[8];
    const float* boff  = (const float*)d_in[9];
    const float* Wa    = (const float*)d_in[10];
    const float* ba    = (const float*)d_in[11];
    const float* Wo    = (const float*)d_in[12];
    const float* bo    = (const float*)d_in[13];
    float* out = (float*)d_out;

    float *Q, *K, *V, *OL, *bc;
    __nv_bfloat16 *Wh, *Wl, *Wch, *Wcl, *Ah, *Al;
    cudaGetSymbolAddress((void**)&Q,   g_Q);
    cudaGetSymbolAddress((void**)&K,   g_K);
    cudaGetSymbolAddress((void**)&V,   g_V);
    cudaGetSymbolAddress((void**)&OL,  g_OL);
    cudaGetSymbolAddress((void**)&bc,  g_bc);
    cudaGetSymbolAddress((void**)&Wh,  g_Wh);
    cudaGetSymbolAddress((void**)&Wl,  g_Wl);
    cudaGetSymbolAddress((void**)&Wch, g_Wch);
    cudaGetSymbolAddress((void**)&Wcl, g_Wcl);
    cudaGetSymbolAddress((void**)&Ah,  g_Ah);
    cudaGetSymbolAddress((void**)&Al,  g_Al);

    cudaFuncSetAttribute(gemm_mma, cudaFuncAttributeMaxDynamicSharedMemorySize,
                         GEMM_SMEM);

    const int WSZ = DM * DM;
    const size_t ASZ = (size_t)ROWS * DM;
    const int AGRID = (int)(ASZ / 1024);

    dim3 gg(DM / 128, ROWS / 128);   // (4, 128)
    dim3 gol(1, ROWS / 128);         // (1, 128) skinny offsets/logits GEMM

    // 0-2: conversions
    conv_bf16<<<AGRID, 256>>>(q_in,  Ah,       Al);
    conv_bf16<<<AGRID, 256>>>(kv_in, Ah + ASZ, Al + ASZ);
    conv_weights<<<1089, 256>>>(Wq, Wk, Wv, Wo, Woff, Wa, boff, ba,
                                Wh, Wl, Wch, Wcl, bc);

    // 3: gemm Q  <- ncu capture slot
    gemm_mma<<<gg, 256, GEMM_SMEM>>>(Ah, Al, Wh, Wl, bq, Q, DM);
    // 4-5: gemm K, V
    gemm_mma<<<gg, 256, GEMM_SMEM>>>(Ah + ASZ, Al + ASZ,
                                     Wh + 1 * WSZ, Wl + 1 * WSZ, bk, K, DM);
    gemm_mma<<<gg, 256, GEMM_SMEM>>>(Ah + ASZ, Al + ASZ,
                                     Wh + 2 * WSZ, Wl + 2 * WSZ, bv, V, DM);
    // 6: offsets + logits as a skinny GEMM (replaces proj_small)
    gemm_mma<<<gol, 256, GEMM_SMEM>>>(Ah, Al, Wch, Wcl, bc, OL, 128);

    // 7: attention; writes bf16 hi/lo split directly into activation buffer 0
    deform_attn<<<(ROWS * NH) / 8, 256>>>(Q, K, V, OL, Ah, Al);

    // 8: output projection
    gemm_mma<<<gg, 256, GEMM_SMEM>>>(Ah, Al, Wh + 3 * WSZ, Wl + 3 * WSZ,
                                     bo, out, DM);
}

// round 12
// speedup vs baseline: 4.2388x; 1.0001x over previous
#include <cuda_runtime.h>
#include <cuda_bf16.h>
#include <math.h>
#include <stdint.h>

// Problem constants (fixed by the dataset)
#define BATCH 4
#define SEQ   4096
#define DM    512
#define NH    8
#define NP    4
#define HD    64              // DM / NH
#define ROWS  (BATCH * SEQ)   // 16384

// ---------------------------------------------------------------------------
// Scratch (device globals; no allocation allowed in kernel_launch)
// ---------------------------------------------------------------------------
__device__ __align__(16) float g_Q  [ROWS * DM];
__device__ __align__(16) float g_K  [ROWS * DM];
__device__ __align__(16) float g_V  [ROWS * DM];
__device__ __align__(16) float g_OL [ROWS * 128];      // cols 0-31 OFF, 32-63 LOG
__device__ __align__(16) float g_bc [128];             // combined bias
// bf16 hi/lo splits: 4 big weights, combined (Woff;Wa;0) weight, 2 activations
__device__ __align__(16) __nv_bfloat16 g_Wh[4][DM * DM];
__device__ __align__(16) __nv_bfloat16 g_Wl[4][DM * DM];
__device__ __align__(16) __nv_bfloat16 g_Wch[128 * DM];
__device__ __align__(16) __nv_bfloat16 g_Wcl[128 * DM];
__device__ __align__(16) __nv_bfloat16 g_Ah[2][ROWS * DM];
__device__ __align__(16) __nv_bfloat16 g_Al[2][ROWS * DM];

// ---------------------------------------------------------------------------
// PTX helpers (baseline sm_80-class features only — valid at .target sm_103)
// ---------------------------------------------------------------------------
__device__ __forceinline__ uint32_t smem_u32(const void* p) {
    uint32_t a;
    asm("{ .reg .u64 t; cvta.to.shared.u64 t, %1; cvt.u32.u64 %0, t; }" : "=r"(a) : "l"(p));
    return a;
}
__device__ __forceinline__ void cp16(uint32_t s, const void* g) {
    asm volatile("cp.async.cg.shared.global [%0], [%1], 16;" :: "r"(s), "l"(g));
}
#define CP_COMMIT()   asm volatile("cp.async.commit_group;" ::: "memory")
#define CP_WAIT(n)    asm volatile("cp.async.wait_group %0;" :: "n"(n) : "memory")

#define LDSM4(r, a) \
    asm volatile("ldmatrix.sync.aligned.m8n8.x4.shared.b16 {%0,%1,%2,%3}, [%4];" \
                 : "=r"((r)[0]), "=r"((r)[1]), "=r"((r)[2]), "=r"((r)[3]) : "r"(a))
#define LDSM2(r, a) \
    asm volatile("ldmatrix.sync.aligned.m8n8.x2.shared.b16 {%0,%1}, [%2];" \
                 : "=r"((r)[0]), "=r"((r)[1]) : "r"(a))

#define MMA_BF16(d, a, b) \
    asm volatile("mma.sync.aligned.m16n8k16.row.col.f32.bf16.bf16.f32 " \
                 "{%0,%1,%2,%3}, {%4,%5,%6,%7}, {%8,%9}, {%0,%1,%2,%3};" \
                 : "+f"((d)[0]), "+f"((d)[1]), "+f"((d)[2]), "+f"((d)[3]) \
                 : "r"((a)[0]), "r"((a)[1]), "r"((a)[2]), "r"((a)[3]), \
                   "r"((b)[0]), "r"((b)[1]))

// fp32x4 -> bf16 hi/lo split, stored as uint2 pairs
__device__ __forceinline__ void split_store4(const float4 f,
                                             __nv_bfloat16* __restrict__ ph,
                                             __nv_bfloat16* __restrict__ pl)
{
    __nv_bfloat162 h01 = __floats2bfloat162_rn(f.x, f.y);
    __nv_bfloat162 h23 = __floats2bfloat162_rn(f.z, f.w);
    float2 a = __bfloat1622float2(h01);
    float2 b = __bfloat1622float2(h23);
    __nv_bfloat162 l01 = __floats2bfloat162_rn(f.x - a.x, f.y - a.y);
    __nv_bfloat162 l23 = __floats2bfloat162_rn(f.z - b.x, f.w - b.y);
    uint2 hv, lv;
    hv.x = *(uint32_t*)&h01; hv.y = *(uint32_t*)&h23;
    lv.x = *(uint32_t*)&l01; lv.y = *(uint32_t*)&l23;
    *(uint2*)ph = hv;
    *(uint2*)pl = lv;
}

// ---------------------------------------------------------------------------
// Activation split: fp32 -> bf16 hi/lo (elementwise)
// ---------------------------------------------------------------------------
__global__ __launch_bounds__(256)
void conv_bf16(const float* __restrict__ X,
               __nv_bfloat16* __restrict__ Xh,
               __nv_bfloat16* __restrict__ Xl)
{
    const size_t i = ((size_t)blockIdx.x * 256 + threadIdx.x) * 4;
    split_store4(*(const float4*)(X + i), Xh + i, Xl + i);
}

// ---------------------------------------------------------------------------
// All weight conversions in one launch:
//   blocks    0..1023: Wq/Wk/Wv/Wo -> g_Wh/g_Wl  (256 blocks each)
//   blocks 1024..1087: combined (Woff rows 0-31, Wa rows 32-63, zeros 64-127)
//   block  1088      : combined bias
// ---------------------------------------------------------------------------
__global__ __launch_bounds__(256)
void conv_weights(const float* __restrict__ Wq, const float* __restrict__ Wk,
                  const float* __restrict__ Wv, const float* __restrict__ Wo,
                  const float* __restrict__ Woff, const float* __restrict__ Wa,
                  const float* __restrict__ boff, const float* __restrict__ ba,
                  __nv_bfloat16* __restrict__ Wh, __nv_bfloat16* __restrict__ Wl,
                  __nv_bfloat16* __restrict__ Wch, __nv_bfloat16* __restrict__ Wcl,
                  float* __restrict__ bc)
{
    const int blk = blockIdx.x;
    if (blk < 1024) {
        const int m = blk >> 8;
        const float* W = (m == 0) ? Wq : (m == 1) ? Wk : (m == 2) ? Wv : Wo;
        const size_t i = ((size_t)(blk & 255) * 256 + threadIdx.x) * 4;
        split_store4(*(const float4*)(W + i),
                     Wh + (size_t)m * DM * DM + i,
                     Wl + (size_t)m * DM * DM + i);
    } else if (blk < 1088) {
        const size_t i = ((size_t)(blk - 1024) * 256 + threadIdx.x) * 4;
        const int row = (int)(i >> 9);
        const int ck  = (int)(i & 511);
        float4 f = make_float4(0.f, 0.f, 0.f, 0.f);
        if (row < 32)       f = *(const float4*)(Woff + (size_t)row * DM + ck);
        else if (row < 64)  f = *(const float4*)(Wa + (size_t)(row - 32) * DM + ck);
        split_store4(f, Wch + i, Wcl + i);
    } else {
        const int n = threadIdx.x;
        if (n < 128)
            bc[n] = (n < 32) ? boff[n] : (n < 64) ? ba[n - 32] : 0.f;
    }
}

// ---------------------------------------------------------------------------
// Tensor-core GEMM (NT): C[m,n] = sum_k A[m,k]*B[n,k] + bias[n]
// fp32 emulated via 3-pass bf16: Ah*Bh + Ah*Bl + Al*Bh (all pre-split).
// Tile 128x128, BK=32, 256 threads (8 warps, 2x4), m16n8k16 fragments.
// 3-stage cp.async pipeline, one __syncthreads per chunk. ldc = C row stride.
// ---------------------------------------------------------------------------
#define ROWB   80                  // bytes per 32-bf16 SMEM row (64B data + pad)
#define TILE_B (128 * ROWB)        // 10240 B per operand tile
#define STG_B  (4 * TILE_B)        // 40960 B: Ah | Al | Bh | Bl
#define NSTAGE 3
#define GEMM_SMEM (NSTAGE * STG_B) // 122880 B

__global__ __launch_bounds__(256)
void gemm_mma(const __nv_bfloat16* __restrict__ Ah,
              const __nv_bfloat16* __restrict__ Al,
              const __nv_bfloat16* __restrict__ Bh,
              const __nv_bfloat16* __restrict__ Bl,
              const float* __restrict__ bias,
              float* __restrict__ C, int ldc)
{
    extern __shared__ char sm[];
    const uint32_t sb = smem_u32(sm);
    const int tid  = threadIdx.x;
    const int lane = tid & 31;
    const int wid  = tid >> 5;
    const int wr   = wid >> 2;     // warp row 0..1  (64 rows each)
    const int wc   = wid & 3;      // warp col 0..3  (32 cols each)

    const int bm = blockIdx.y * 128;
    const int bn = blockIdx.x * 128;

    const __nv_bfloat16* gAh = Ah + (size_t)bm * DM;
    const __nv_bfloat16* gAl = Al + (size_t)bm * DM;
    const __nv_bfloat16* gBh = Bh + (size_t)bn * DM;
    const __nv_bfloat16* gBl = Bl + (size_t)bn * DM;

    float acc[4][4][4];
#pragma unroll
    for (int i = 0; i < 4; i++)
#pragma unroll
        for (int j = 0; j < 4; j++)
#pragma unroll
            for (int k = 0; k < 4; k++) acc[i][j][k] = 0.0f;

    const int srow = tid >> 1;
#define STAGE(cc, sbuf) do {                                                  \
        const uint32_t buf = sb + (uint32_t)(sbuf) * STG_B;                   \
        const int kb = (cc) * 32;                                             \
        _Pragma("unroll")                                                     \
        for (int jj = 0; jj < 2; jj++) {                                      \
            const int j = (tid & 1) + jj * 2;                                 \
            const size_t go = (size_t)srow * DM + kb + j * 8;                 \
            const uint32_t so = (uint32_t)(srow * ROWB + j * 16);             \
            cp16(buf + so,              gAh + go);                            \
            cp16(buf + TILE_B + so,     gAl + go);                            \
            cp16(buf + 2*TILE_B + so,   gBh + go);                            \
            cp16(buf + 3*TILE_B + so,   gBl + go);                            \
        }                                                                     \
        CP_COMMIT();                                                          \
    } while (0)

    STAGE(0, 0);
    STAGE(1, 1);

    const int al15 = lane & 15;
    const int ac   = lane >> 4;
    const int bl7  = lane & 7;
    const int bc   = (lane >> 3) & 1;

    int rbuf = 0, wbuf = 2;
    for (int c = 0; c < 16; c++) {
        if (c < 15) { CP_WAIT(1); } else { CP_WAIT(0); }
        __syncthreads();
        if (c + 2 < 16) STAGE(c + 2, wbuf);

        const uint32_t buf  = sb + (uint32_t)rbuf * STG_B;
        const uint32_t ahB  = buf;
        const uint32_t alB  = buf + TILE_B;
        const uint32_t bhB  = buf + 2 * TILE_B;
        const uint32_t blB  = buf + 3 * TILE_B;

#pragma unroll
        for (int ks = 0; ks < 2; ks++) {
            uint32_t fah[4][4], fal[4][4], fbh[4][2], fbl[4][2];
#pragma unroll
            for (int mt = 0; mt < 4; mt++) {
                const uint32_t off =
                    (uint32_t)((wr * 64 + mt * 16 + al15) * ROWB
                               + (2 * ks + ac) * 16);
                LDSM4(fah[mt], ahB + off);
                LDSM4(fal[mt], alB + off);
            }
#pragma unroll
            for (int nt = 0; nt < 4; nt++) {
                const uint32_t off =
                    (uint32_t)((wc * 32 + nt * 8 + bl7) * ROWB
                               + (2 * ks + bc) * 16);
                LDSM2(fbh[nt], bhB + off);
                LDSM2(fbl[nt], blB + off);
            }
#pragma unroll
            for (int mt = 0; mt < 4; mt++)
#pragma unroll
                for (int nt = 0; nt < 4; nt++)
                    MMA_BF16(acc[mt][nt], fah[mt], fbh[nt]);
#pragma unroll
            for (int mt = 0; mt < 4; mt++)
#pragma unroll
                for (int nt = 0; nt < 4; nt++)
                    MMA_BF16(acc[mt][nt], fah[mt], fbl[nt]);
#pragma unroll
            for (int mt = 0; mt < 4; mt++)
#pragma unroll
                for (int nt = 0; nt < 4; nt++)
                    MMA_BF16(acc[mt][nt], fal[mt], fbh[nt]);
        }

        rbuf = (rbuf == NSTAGE - 1) ? 0 : rbuf + 1;
        wbuf = (wbuf == NSTAGE - 1) ? 0 : wbuf + 1;
    }

    const int gr = lane >> 2;
    const int gc = (lane & 3) * 2;
#pragma unroll
    for (int mt = 0; mt < 4; mt++) {
        const int r0 = bm + wr * 64 + mt * 16 + gr;
#pragma unroll
        for (int nt = 0; nt < 4; nt++) {
            const int c0 = bn + wc * 32 + nt * 8 + gc;
            const float b0 = bias[c0], b1 = bias[c0 + 1];
            float2 v0, v1;
            v0.x = acc[mt][nt][0] + b0; v0.y = acc[mt][nt][1] + b1;
            v1.x = acc[mt][nt][2] + b0; v1.y = acc[mt][nt][3] + b1;
            *(float2*)(C + (size_t)r0 * ldc + c0)       = v0;
            *(float2*)(C + (size_t)(r0 + 8) * ldc + c0) = v1;
        }
    }
#undef STAGE
}

// ---------------------------------------------------------------------------
// Deformable attention core, vectorized.
// One warp per (bl, h). Lanes 0-15 own interpolation row a0, lanes 16-31 own
// a1; lane j holds dims [j*4, j*4+4) as float4. Output is written directly as
// bf16 hi/lo split (feeds the final GEMM without a separate conversion pass).
// ---------------------------------------------------------------------------
__global__ __launch_bounds__(256)
void deform_attn(const float* __restrict__ Q,
                 const float* __restrict__ Kx,
                 const float* __restrict__ Vx,
                 const float* __restrict__ OL,
                 __nv_bfloat16* __restrict__ Oh,
                 __nv_bfloat16* __restrict__ Ol)
{
    const int warp = blockIdx.x * 8 + (threadIdx.x >> 5);
    const int lane = threadIdx.x & 31;
    const int half = lane >> 4;        // 0: row a0, 1: row a1
    const int j    = lane & 15;        // float4 slot within head dim

    const int h  = warp & 7;
    const int bl = warp >> 3;
    const int l  = bl & (SEQ - 1);
    const int b  = bl >> 12;

    const size_t col = (size_t)h * HD + j * 4;
    const float4 qv   = *(const float4*)(Q + (size_t)bl * DM + col);
    const float4 offv = *(const float4*)(OL + (size_t)bl * 128 + h * 4);
    const float4 logv = *(const float4*)(OL + (size_t)bl * 128 + 32 + h * 4);

    const float* Kb = Kx + (size_t)b * SEQ * DM;
    const float* Vb = Vx + (size_t)b * SEQ * DM;

    const float offs[4] = {offv.x, offv.y, offv.z, offv.w};
    const float logs[4] = {logv.x, logv.y, logv.z, logv.w};

    int   r0[4], r1[4];
    float wf[4], dot[4];

#pragma unroll
    for (int p = 0; p < 4; p++) {
        float idx = fminf(fmaxf((float)l + offs[p], 0.0f), (float)(SEQ - 1));
        int   a0  = min((int)idx, SEQ - 1);      // idx >= 0 -> trunc == floor
        int   a1  = min(a0 + 1, SEQ - 1);
        float w   = idx - (float)a0;
        r0[p] = a0; r1[p] = a1; wf[p] = w;

        const int row = half ? a1 : a0;
        const float4 kv = *(const float4*)(Kb + (size_t)row * DM + col);
        float part = qv.x * kv.x + qv.y * kv.y + qv.z * kv.z + qv.w * kv.w;
#pragma unroll
        for (int s = 1; s < 16; s <<= 1)
            part += __shfl_xor_sync(0xffffffffu, part, s);
        const float other = __shfl_xor_sync(0xffffffffu, part, 16);
        const float d0 = half ? other : part;
        const float d1 = half ? part : other;
        dot[p] = ((1.0f - w) * d0 + w * d1) * 0.125f + logs[p];
    }

    // softmax over P=4 (identical in all lanes)
    const float m = fmaxf(fmaxf(dot[0], dot[1]), fmaxf(dot[2], dot[3]));
    float e[4], ss = 0.0f;
#pragma unroll
    for (int p = 0; p < 4; p++) { e[p] = expf(dot[p] - m); ss += e[p]; }
    const float inv = 1.0f / ss;

    float4 acc = make_float4(0.f, 0.f, 0.f, 0.f);
#pragma unroll
    for (int p = 0; p < 4; p++) {
        const int   row  = half ? r1[p] : r0[p];
        const float coef = e[p] * inv * (half ? wf[p] : (1.0f - wf[p]));
        const float4 vv  = *(const float4*)(Vb + (size_t)row * DM + col);
        acc.x += coef * vv.x; acc.y += coef * vv.y;
        acc.z += coef * vv.z; acc.w += coef * vv.w;
    }
    // combine halves
    acc.x += __shfl_xor_sync(0xffffffffu, acc.x, 16);
    acc.y += __shfl_xor_sync(0xffffffffu, acc.y, 16);
    acc.z += __shfl_xor_sync(0xffffffffu, acc.z, 16);
    acc.w += __shfl_xor_sync(0xffffffffu, acc.w, 16);

    if (half == 0) {
        const size_t oi = (size_t)bl * DM + col;
        split_store4(acc, Oh + oi, Ol + oi);
    }
}

// ---------------------------------------------------------------------------
// Launch. ncu captures our launch index 3 -> gemm_mma(Q).
// ---------------------------------------------------------------------------
extern "C" void kernel_launch(void* const* d_in, const int* in_sizes, int n_in,
                              void* d_out, int out_size)
{
    const float* q_in  = (const float*)d_in[0];
    const float* kv_in = (const float*)d_in[1];
    const float* Wq    = (const float*)d_in[2];
    const float* bq    = (const float*)d_in[3];
    const float* Wk    = (const float*)d_in[4];
    const float* bk    = (const float*)d_in[5];
    const float* Wv    = (const float*)d_in[6];
    const float* bv    = (const float*)d_in[7];
    const float* Woff  = (const float*)d_in[8];
    const float* boff  = (const float*)d_in[9];
    const float* Wa    = (const float*)d_in[10];
    const float* ba    = (const float*)d_in[11];
    const float* Wo    = (const float*)d_in[12];
    const float* bo    = (const float*)d_in[13];
    float* out = (float*)d_out;

    float *Q, *K, *V, *OL, *bc;
    __nv_bfloat16 *Wh, *Wl, *Wch, *Wcl, *Ah, *Al;
    cudaGetSymbolAddress((void**)&Q,   g_Q);
    cudaGetSymbolAddress((void**)&K,   g_K);
    cudaGetSymbolAddress((void**)&V,   g_V);
    cudaGetSymbolAddress((void**)&OL,  g_OL);
    cudaGetSymbolAddress((void**)&bc,  g_bc);
    cudaGetSymbolAddress((void**)&Wh,  g_Wh);
    cudaGetSymbolAddress((void**)&Wl,  g_Wl);
    cudaGetSymbolAddress((void**)&Wch, g_Wch);
    cudaGetSymbolAddress((void**)&Wcl, g_Wcl);
    cudaGetSymbolAddress((void**)&Ah,  g_Ah);
    cudaGetSymbolAddress((void**)&Al,  g_Al);

    cudaFuncSetAttribute(gemm_mma, cudaFuncAttributeMaxDynamicSharedMemorySize,
                         GEMM_SMEM);

    const int WSZ = DM * DM;
    const size_t ASZ = (size_t)ROWS * DM;
    const int AGRID = (int)(ASZ / 1024);

    dim3 gg(DM / 128, ROWS / 128);   // (4, 128)
    dim3 gol(1, ROWS / 128);         // (1, 128) skinny offsets/logits GEMM

    // 0-2: conversions
    conv_bf16<<<AGRID, 256>>>(q_in,  Ah,       Al);
    conv_bf16<<<AGRID, 256>>>(kv_in, Ah + ASZ, Al + ASZ);
    conv_weights<<<1089, 256>>>(Wq, Wk, Wv, Wo, Woff, Wa, boff, ba,
                                Wh, Wl, Wch, Wcl, bc);

    // 3: gemm Q  <- ncu capture slot
    gemm_mma<<<gg, 256, GEMM_SMEM>>>(Ah, Al, Wh, Wl, bq, Q, DM);
    // 4-5: gemm K, V
    gemm_mma<<<gg, 256, GEMM_SMEM>>>(Ah + ASZ, Al + ASZ,
                                     Wh + 1 * WSZ, Wl + 1 * WSZ, bk, K, DM);
    gemm_mma<<<gg, 256, GEMM_SMEM>>>(Ah + ASZ, Al + ASZ,
                                     Wh + 2 * WSZ, Wl + 2 * WSZ, bv, V, DM);
    // 6: offsets + logits as a skinny GEMM (replaces proj_small)
    gemm_mma<<<gol, 256, GEMM_SMEM>>>(Ah, Al, Wch, Wcl, bc, OL, 128);

    // 7: attention; writes bf16 hi/lo split directly into activation buffer 0
    deform_attn<<<(ROWS * NH) / 8, 256>>>(Q, K, V, OL, Ah, Al);

    // 8: output projection
    gemm_mma<<<gg, 256, GEMM_SMEM>>>(Ah, Al, Wh + 3 * WSZ, Wl + 3 * WSZ,
                                     bo, out, DM);
}